// round 1
// baseline (speedup 1.0000x reference)
#include <cuda_runtime.h>
#include <math.h>

// Problem constants
#define NB      4
#define NGRID   512
#define NTARGET 1024
#define NBASIS  5
#define NCH     8

// Device scratch (no cudaMalloc allowed)
__device__ int   d_nuniq[NCH];
__device__ int   d_grp[NCH][NBASIS];
__device__ float d_sc[NCH][NBASIS];                       // sqrt(0.5*log2e)/s per (c,u)
__device__ float d_hsum[NBASIS * NB * NGRID * NCH];       // [u][b][g][c]

// ---------------------------------------------------------------------------
// Prep A: per-channel scale dedup.  scales = exp(sigma)+EPS; group equal
// scales so the exp weight is computed once per unique scale, not per basis.
// ---------------------------------------------------------------------------
__global__ void prep_scales(const float* __restrict__ sigma /* [NBASIS][NCH] */) {
    if (threadIdx.x != 0 || blockIdx.x != 0) return;
    const float C = 0.8493218002880190f;  // sqrt(0.5 * log2(e))
    for (int c = 0; c < NCH; ++c) {
        float s[NBASIS], uniq[NBASIS];
        int grp[NBASIS], nu = 0;
        for (int k = 0; k < NBASIS; ++k)
            s[k] = expf(sigma[k * NCH + c]) + 1e-6f;
        for (int k = 0; k < NBASIS; ++k) {
            int u = -1;
            for (int j = 0; j < nu; ++j)
                if (uniq[j] == s[k]) { u = j; break; }
            if (u < 0) { u = nu; uniq[nu++] = s[k]; }
            grp[k] = u;
        }
        d_nuniq[c] = nu;
        for (int k = 0; k < NBASIS; ++k) d_grp[c][k] = grp[k];
        for (int u = 0; u < nu; ++u)     d_sc[c][u] = C / uniq[u];
    }
}

// ---------------------------------------------------------------------------
// Prep B: fold g_w into per-scale-group sums of h_grid.
// d_hsum[u][b][g][c] = sum_{k: grp[c][k]==u} h_grid[b][g][k][c] * g_w[k]
// ---------------------------------------------------------------------------
__global__ void prep_hsum(const float* __restrict__ h_grid,  // [NB][NGRID][NBASIS][NCH]
                          const float* __restrict__ g_w) {   // [1][NBASIS]
    int i = blockIdx.x * blockDim.x + threadIdx.x;  // over (b,g)
    if (i >= NB * NGRID) return;
    float gw[NBASIS];
#pragma unroll
    for (int k = 0; k < NBASIS; ++k) gw[k] = g_w[k];
    for (int c = 0; c < NCH; ++c) {
        int nu = d_nuniq[c];
        float acc[NBASIS] = {0.f, 0.f, 0.f, 0.f, 0.f};
#pragma unroll
        for (int k = 0; k < NBASIS; ++k)
            acc[d_grp[c][k]] += h_grid[(i * NBASIS + k) * NCH + c] * gw[k];
        for (int u = 0; u < nu; ++u)
            d_hsum[(u * (NB * NGRID) + i) * NCH + c] = acc[u];
    }
}

// ---------------------------------------------------------------------------
// Main: out[b,t,c] = g_b + sum_u sum_g exp2(-(sc_u*(x[b,g,c]-t[b,t,c]))^2)
//                                      * hsum[u,b,g,c]
// Block = 128 threads = 16 targets x 8 channels (each warp: 2 channels x 16 t).
// Grid  = NB * (NTARGET/16) = 256 blocks.
// ---------------------------------------------------------------------------
__global__ void __launch_bounds__(128)
finallayer_main(const float* __restrict__ x_grid,    // [NB][NGRID][NCH]
                const float* __restrict__ target_x,  // [NB][NTARGET][NCH]
                const float* __restrict__ g_b,       // [1]
                float* __restrict__ out)             // [NB][NTARGET][NCH]
{
    __shared__ float2 pair[NGRID * NCH];  // (x, hsum_u0) interleaved, 32 KB

    const int b    = blockIdx.x >> 6;          // 64 tiles per batch
    const int tile = blockIdx.x & 63;

    const float* xg  = x_grid + b * (NGRID * NCH);
    const float* hs0 = d_hsum + b * (NGRID * NCH);  // u = 0 slice
    for (int i = threadIdx.x; i < NGRID * NCH; i += 128)
        pair[i] = make_float2(xg[i], hs0[i]);
    __syncthreads();

    const int lane = threadIdx.x & 31;
    const int c    = ((threadIdx.x >> 5) << 1) | (lane >> 4);  // 0..7
    const int t    = tile * 16 + (lane & 15);

    const float tv  = __ldg(&target_x[(b * NTARGET + t) * NCH + c]);
    float acc = __ldg(g_b);
    const int nu = d_nuniq[c];

    // u = 0 fast path (data in shared)
    {
        const float sc   = d_sc[c][0];
        const float ntsc = -tv * sc;
#pragma unroll 8
        for (int g = 0; g < NGRID; ++g) {
            float2 p  = pair[g * NCH + c];
            float ds  = fmaf(p.x, sc, ntsc);
            float arg = -ds * ds;
            float wv;
            asm("ex2.approx.ftz.f32 %0, %1;" : "=f"(wv) : "f"(arg));
            acc = fmaf(wv, p.y, acc);
        }
    }
    // Remaining unique scales (generic path; not taken for uniform sigma)
    for (int u = 1; u < nu; ++u) {
        const float sc   = d_sc[c][u];
        const float ntsc = -tv * sc;
        const float* hsu = d_hsum + (u * NB + b) * (NGRID * NCH) + c;
#pragma unroll 4
        for (int g = 0; g < NGRID; ++g) {
            float xv  = pair[g * NCH + c].x;
            float hv  = __ldg(&hsu[g * NCH]);
            float ds  = fmaf(xv, sc, ntsc);
            float arg = -ds * ds;
            float wv;
            asm("ex2.approx.ftz.f32 %0, %1;" : "=f"(wv) : "f"(arg));
            acc = fmaf(wv, hv, acc);
        }
    }

    out[(b * NTARGET + t) * NCH + c] = acc;
}

// ---------------------------------------------------------------------------
extern "C" void kernel_launch(void* const* d_in, const int* in_sizes, int n_in,
                              void* d_out, int out_size) {
    const float* x_grid   = (const float*)d_in[0];  // [4,512,8]
    const float* h_grid   = (const float*)d_in[1];  // [4,512,5,8]
    const float* target_x = (const float*)d_in[2];  // [4,1024,8]
    const float* sigma    = (const float*)d_in[3];  // [5,8]
    const float* g_w      = (const float*)d_in[4];  // [1,5]
    const float* g_b      = (const float*)d_in[5];  // [1]
    float* out = (float*)d_out;                     // [4,1024,8]

    prep_scales<<<1, 32>>>(sigma);
    prep_hsum<<<(NB * NGRID + 255) / 256, 256>>>(h_grid, g_w);
    finallayer_main<<<NB * (NTARGET / 16), 128>>>(x_grid, target_x, g_b, out);
}

// round 2
// speedup vs baseline: 1.2358x; 1.2358x over previous
#include <cuda_runtime.h>
#include <math.h>

#define NB      4
#define NGRID   512
#define NTARGET 1024
#define NBASIS  5
#define NCH     8
#define GSTRIDE (NGRID + 2)   // +2 float2 pad: de-conflicts the two half-warp channels

// Single fused kernel.
// Grid = NB * (NTARGET/16) = 256 blocks, 128 threads = 16 targets x 8 channels.
// out[b,t,c] = g_b + sum_u sum_g exp2(-(sc_u*(x[g,c]-t))^2) * hsum_u[g,c]
// where scales are deduped per channel (uniform sigma -> nu=1, 5x fewer exp).
__global__ void __launch_bounds__(128)
finallayer_fused(const float* __restrict__ x_grid,    // [NB][NGRID][NCH]
                 const float* __restrict__ h_grid,    // [NB][NGRID][NBASIS][NCH]
                 const float* __restrict__ target_x,  // [NB][NTARGET][NCH]
                 const float* __restrict__ sigma,     // [NBASIS][NCH]
                 const float* __restrict__ g_w,       // [1][NBASIS]
                 const float* __restrict__ g_b,       // [1]
                 float* __restrict__ out)             // [NB][NTARGET][NCH]
{
    __shared__ __align__(16) float2 pairs[NCH][GSTRIDE];  // (x*sc0, hsum0), per-channel rows
    __shared__ float s_sc[NCH][NBASIS];
    __shared__ int   s_grp[NCH][NBASIS];
    __shared__ int   s_nu[NCH];
    __shared__ float s_gw[NBASIS];
    __shared__ float s_gb;

    const int tid  = threadIdx.x;
    const int b    = blockIdx.x >> 6;   // 64 target-tiles per batch
    const int tile = blockIdx.x & 63;

    // --- per-channel scale dedup (redundant per block, trivial cost) ---
    if (tid < NCH) {
        const float C = 0.8493218002880190f;  // sqrt(0.5 * log2(e))
        float s[NBASIS], uniq[NBASIS];
        int nu = 0;
#pragma unroll
        for (int k = 0; k < NBASIS; ++k)
            s[k] = expf(sigma[k * NCH + tid]) + 1e-6f;
#pragma unroll
        for (int k = 0; k < NBASIS; ++k) {
            int u = -1;
            for (int j = 0; j < nu; ++j)
                if (uniq[j] == s[k]) { u = j; break; }
            if (u < 0) { u = nu; uniq[nu++] = s[k]; }
            s_grp[tid][k] = u;
        }
        s_nu[tid] = nu;
        for (int u = 0; u < nu; ++u) s_sc[tid][u] = C / uniq[u];
    } else if (tid < NCH + NBASIS) {
        s_gw[tid - NCH] = g_w[tid - NCH];
    } else if (tid == NCH + NBASIS) {
        s_gb = g_b[0];
    }
    __syncthreads();

    // --- cooperative fill: x pre-scaled by sc0, hsum0 folded from h*g_w ---
    const float* xg = x_grid + b * (NGRID * NCH);
    const float* hg = h_grid + b * (NGRID * NBASIS * NCH);
    for (int i = tid; i < NGRID * NCH; i += 128) {
        const int c = i & 7, g = i >> 3;
        float acc = 0.f;
#pragma unroll
        for (int k = 0; k < NBASIS; ++k)
            if (s_grp[c][k] == 0)
                acc += hg[(g * NBASIS + k) * NCH + c] * s_gw[k];
        pairs[c][g] = make_float2(xg[i] * s_sc[c][0], acc);
    }
    __syncthreads();

    // --- main loop ---
    const int lane = tid & 31;
    const int c    = ((tid >> 5) << 1) | (lane >> 4);  // 2 channels per warp
    const int t    = tile * 16 + (lane & 15);

    const float tv  = __ldg(&target_x[(b * NTARGET + t) * NCH + c]);
    const float ts0 = tv * s_sc[c][0];
    float acc = s_gb;

    const float4* pc = (const float4*)&pairs[c][0];  // 2 grid points per LDS.128
#pragma unroll 8
    for (int gg = 0; gg < NGRID / 2; ++gg) {
        float4 q = pc[gg];               // (x0*sc, h0, x1*sc, h1)
        float d0 = q.x - ts0;
        float d1 = q.z - ts0;
        float a0 = -d0 * d0;
        float a1 = -d1 * d1;
        float w0, w1;
        asm("ex2.approx.ftz.f32 %0, %1;" : "=f"(w0) : "f"(a0));
        asm("ex2.approx.ftz.f32 %0, %1;" : "=f"(w1) : "f"(a1));
        acc = fmaf(w0, q.y, acc);
        acc = fmaf(w1, q.w, acc);
    }

    // --- generic cold path: extra unique scales (not taken for uniform sigma) ---
    const int nu = s_nu[c];
    for (int u = 1; u < nu; ++u) {
        const float sc  = s_sc[c][u];
        const float nts = -tv * sc;
        for (int g = 0; g < NGRID; ++g) {
            float xv = __ldg(&xg[g * NCH + c]);
            float hv = 0.f;
#pragma unroll
            for (int k = 0; k < NBASIS; ++k)
                if (s_grp[c][k] == u)
                    hv += __ldg(&hg[(g * NBASIS + k) * NCH + c]) * s_gw[k];
            float ds = fmaf(xv, sc, nts);
            float a  = -ds * ds;
            float w;
            asm("ex2.approx.ftz.f32 %0, %1;" : "=f"(w) : "f"(a));
            acc = fmaf(w, hv, acc);
        }
    }

    out[(b * NTARGET + t) * NCH + c] = acc;
}

// ---------------------------------------------------------------------------
extern "C" void kernel_launch(void* const* d_in, const int* in_sizes, int n_in,
                              void* d_out, int out_size) {
    const float* x_grid   = (const float*)d_in[0];  // [4,512,8]
    const float* h_grid   = (const float*)d_in[1];  // [4,512,5,8]
    const float* target_x = (const float*)d_in[2];  // [4,1024,8]
    const float* sigma    = (const float*)d_in[3];  // [5,8]
    const float* g_w      = (const float*)d_in[4];  // [1,5]
    const float* g_b      = (const float*)d_in[5];  // [1]
    float* out = (float*)d_out;                     // [4,1024,8]

    finallayer_fused<<<NB * (NTARGET / 16), 128>>>(
        x_grid, h_grid, target_x, sigma, g_w, g_b, out);
}

// round 3
// speedup vs baseline: 1.6416x; 1.3283x over previous
#include <cuda_runtime.h>
#include <math.h>

#define NB      4
#define NGRID   512
#define NTARGET 1024
#define NBASIS  5
#define NCH     8

#define SPLIT   8                 // NGRID split factor
#define CHUNK   (NGRID / SPLIT)   // 64 grid points per block
#define TILES   16                // target tiles per batch (64 targets each)
#define TPT     4                 // targets per thread

// Partial sums: [SPLIT][NB][NTARGET][NCH]  (1 MB device scratch)
__device__ float d_part[SPLIT * NB * NTARGET * NCH];

// ---------------------------------------------------------------------------
// Main kernel: each block = (batch b, target tile of 64, grid chunk of 64).
// Block 128 threads: warp w covers channels {2w, 2w+1}; lanes 0-15 -> c0,
// lanes 16-31 -> c1; each thread handles 4 targets (t, t+16, t+32, t+48).
// Writes partial sum over its grid chunk to d_part.
// ---------------------------------------------------------------------------
__global__ void __launch_bounds__(128)
finallayer_partial(const float* __restrict__ x_grid,    // [NB][NGRID][NCH]
                   const float* __restrict__ h_grid,    // [NB][NGRID][NBASIS][NCH]
                   const float* __restrict__ target_x,  // [NB][NTARGET][NCH]
                   const float* __restrict__ sigma,     // [NBASIS][NCH]
                   const float* __restrict__ g_w)       // [1][NBASIS]
{
    __shared__ __align__(16) float2 pairs[NCH][CHUNK];  // (x*sc0, hsum0), 4 KB
    __shared__ float s_sc[NCH][NBASIS];
    __shared__ int   s_grp[NCH][NBASIS];
    __shared__ int   s_nu[NCH];
    __shared__ float s_gw[NBASIS];

    const int tid   = threadIdx.x;
    const int chunk = blockIdx.x & (SPLIT - 1);
    const int tile  = (blockIdx.x >> 3) & (TILES - 1);
    const int b     = blockIdx.x >> 7;           // blockIdx = b*128 + tile*8 + chunk
    const int g0    = chunk * CHUNK;

    // --- per-channel scale dedup (redundant per block, trivial) ---
    if (tid < NCH) {
        const float C = 0.8493218002880190f;     // sqrt(0.5 * log2(e))
        float s[NBASIS], uniq[NBASIS];
        int nu = 0;
#pragma unroll
        for (int k = 0; k < NBASIS; ++k)
            s[k] = expf(sigma[k * NCH + tid]) + 1e-6f;
#pragma unroll
        for (int k = 0; k < NBASIS; ++k) {
            int u = -1;
            for (int j = 0; j < nu; ++j)
                if (uniq[j] == s[k]) { u = j; break; }
            if (u < 0) { u = nu; uniq[nu++] = s[k]; }
            s_grp[tid][k] = u;
        }
        s_nu[tid] = nu;
        for (int u = 0; u < nu; ++u) s_sc[tid][u] = C / uniq[u];
    } else if (tid < NCH + NBASIS) {
        s_gw[tid - NCH] = g_w[tid - NCH];
    }
    __syncthreads();

    // --- fill chunk: x pre-scaled by sc0, hsum0 folded from h*g_w ---
    const float* xg = x_grid + (b * NGRID + g0) * NCH;
    const float* hg = h_grid + (b * NGRID + g0) * NBASIS * NCH;
    for (int i = tid; i < CHUNK * NCH; i += 128) {
        const int c = i & 7, g = i >> 3;
        float acc = 0.f;
#pragma unroll
        for (int k = 0; k < NBASIS; ++k)
            if (s_grp[c][k] == 0)
                acc += hg[(g * NBASIS + k) * NCH + c] * s_gw[k];
        pairs[c][g] = make_float2(xg[i] * s_sc[c][0], acc);
    }
    __syncthreads();

    // --- main loop: 4 targets per thread, 2 grid points per LDS.128 ---
    const int lane = tid & 31;
    const int c    = ((tid >> 5) << 1) | (lane >> 4);
    const int tb   = tile * 64 + (lane & 15);    // targets tb + 16*j

    float ts[TPT], acc[TPT];
#pragma unroll
    for (int j = 0; j < TPT; ++j) {
        float tv = __ldg(&target_x[(b * NTARGET + tb + 16 * j) * NCH + c]);
        ts[j]  = tv * s_sc[c][0];
        acc[j] = 0.f;
    }

    const float4* pc = (const float4*)&pairs[c][0];
#pragma unroll 4
    for (int gg = 0; gg < CHUNK / 2; ++gg) {
        float4 q = pc[gg];                       // (x0*sc, h0, x1*sc, h1)
#pragma unroll
        for (int j = 0; j < TPT; ++j) {
            float d0 = q.x - ts[j];
            float d1 = q.z - ts[j];
            float a0 = -d0 * d0;
            float a1 = -d1 * d1;
            float w0, w1;
            asm("ex2.approx.ftz.f32 %0, %1;" : "=f"(w0) : "f"(a0));
            asm("ex2.approx.ftz.f32 %0, %1;" : "=f"(w1) : "f"(a1));
            acc[j] = fmaf(w0, q.y, acc[j]);
            acc[j] = fmaf(w1, q.w, acc[j]);
        }
    }

    // --- generic cold path: extra unique scales (not taken for uniform sigma) ---
    const int nu = s_nu[c];
    for (int u = 1; u < nu; ++u) {
        const float sc = s_sc[c][u];
        for (int g = 0; g < CHUNK; ++g) {
            float xv = __ldg(&xg[g * NCH + c]);
            float hv = 0.f;
#pragma unroll
            for (int k = 0; k < NBASIS; ++k)
                if (s_grp[c][k] == u)
                    hv += __ldg(&hg[(g * NBASIS + k) * NCH + c]) * s_gw[k];
            float xs = xv * sc;
#pragma unroll
            for (int j = 0; j < TPT; ++j) {
                float tvs = __ldg(&target_x[(b * NTARGET + tb + 16 * j) * NCH + c]) * sc;
                float ds  = xs - tvs;
                float a   = -ds * ds;
                float w;
                asm("ex2.approx.ftz.f32 %0, %1;" : "=f"(w) : "f"(a));
                acc[j] = fmaf(w, hv, acc[j]);
            }
        }
    }

#pragma unroll
    for (int j = 0; j < TPT; ++j)
        d_part[((chunk * NB + b) * NTARGET + tb + 16 * j) * NCH + c] = acc[j];
}

// ---------------------------------------------------------------------------
// Reduce: out[i] = g_b + sum over SPLIT partials
// ---------------------------------------------------------------------------
__global__ void __launch_bounds__(256)
finallayer_reduce(const float* __restrict__ g_b, float* __restrict__ out)
{
    const int i = blockIdx.x * 256 + threadIdx.x;   // 0 .. NB*NTARGET*NCH-1
    float acc = __ldg(g_b);
#pragma unroll
    for (int s = 0; s < SPLIT; ++s)
        acc += d_part[s * (NB * NTARGET * NCH) + i];
    out[i] = acc;
}

// ---------------------------------------------------------------------------
extern "C" void kernel_launch(void* const* d_in, const int* in_sizes, int n_in,
                              void* d_out, int out_size) {
    const float* x_grid   = (const float*)d_in[0];  // [4,512,8]
    const float* h_grid   = (const float*)d_in[1];  // [4,512,5,8]
    const float* target_x = (const float*)d_in[2];  // [4,1024,8]
    const float* sigma    = (const float*)d_in[3];  // [5,8]
    const float* g_w      = (const float*)d_in[4];  // [1,5]
    const float* g_b      = (const float*)d_in[5];  // [1]
    float* out = (float*)d_out;                     // [4,1024,8]

    finallayer_partial<<<NB * TILES * SPLIT, 128>>>(
        x_grid, h_grid, target_x, sigma, g_w);
    finallayer_reduce<<<(NB * NTARGET * NCH) / 256, 256>>>(g_b, out);
}